// round 13
// baseline (speedup 1.0000x reference)
// Round 12 submission. Theory (kept as comments so the harness cannot
// mis-extract prose):
//
// Post-mortem rounds 8/10: the submission pipeline extracted prose instead of
// code; from now on the reply contains ONLY this fenced block.
//
// Theory (unchanged since round 7): attn_sums (62.6us, tensor 43.7%, issue
// 47%) and attn_write (~120us) serialize gmem loads against MMA via
// sync-load/compute/sync chains. Apply the cp.async double-buffer pattern
// already proven in the projection GEMMs:
//  - pass 1 ping-pongs 128-key K chunks (raw fp32 DMA'd, tf32 convert at
//    fragment load, 1/sqrt(dk) applied post-MMA inside the exp);
//  - pass 2 ping-pongs the per-head (Q,K) stage across the head loop so head
//    h+1 loads overlap head h MMA + the 256MB attn store.
// Prediction: sums 62.6 -> ~45us (tensor% -> ~60+); write ~120 -> ~85-90us;
// total 313 -> ~265-275us; rel_err ~5e-4 unchanged. If write stays >100us,
// the streaming store is the wall and the next lever is occupancy/store
// shape, not pipelining.

#include <cuda_runtime.h>
#include <cuda_bf16.h>
#include <math.h>
#include <stdint.h>

#define NB 8
#define SS 1024
#define DD 512
#define NH 8
#define DK 64
#define MROWS (NB * SS)
#define OUT_ELEMS (NB * SS * DD)

__device__ float g_qh[MROWS * DD];
__device__ float g_kh[MROWS * DD];
__device__ float g_vs[MROWS * DK];
__device__ float g_pavg[NB * SS * SS];
__device__ float g_head[MROWS * DK];
__device__ float g_rsuminv[NH * NB * SS];

__device__ __forceinline__ uint32_t f2tf32(float x) {
    uint32_t r;
    asm("cvt.rna.tf32.f32 %0, %1;" : "=r"(r) : "f"(x));
    return r;
}

__device__ __forceinline__ void mma_tf32(float* d, const uint32_t* a,
                                         const uint32_t* b, const float* c) {
    asm volatile(
        "mma.sync.aligned.m16n8k8.row.col.f32.tf32.tf32.f32 "
        "{%0,%1,%2,%3}, {%4,%5,%6,%7}, {%8,%9}, {%10,%11,%12,%13};"
        : "=f"(d[0]), "=f"(d[1]), "=f"(d[2]), "=f"(d[3])
        : "r"(a[0]), "r"(a[1]), "r"(a[2]), "r"(a[3]),
          "r"(b[0]), "r"(b[1]),
          "f"(c[0]), "f"(c[1]), "f"(c[2]), "f"(c[3]));
}

__device__ __forceinline__ void cp_async16(uint32_t dst, const void* src) {
    asm volatile("cp.async.cg.shared.global [%0], [%1], 16;" :: "r"(dst), "l"(src));
}
__device__ __forceinline__ void cp_commit() {
    asm volatile("cp.async.commit_group;");
}
__device__ __forceinline__ void cp_wait1() {
    asm volatile("cp.async.wait_group 1;");
}

// ---------------------------------------------------------------------------
// Pipelined MMA GEMM-NT: C[M,N] = A[M,K] * W[N,K]^T, tf32.
// BM=128, BN=64, BK=32, 2-stage cp.async double buffer. 8 warps (4Mx2N).
// ---------------------------------------------------------------------------
#define GST 36
#define PROJ_STAGE (192 * GST)
#define PROJ_SMEM (2 * PROJ_STAGE * 4)

__global__ __launch_bounds__(256, 2)
void gemm_nt_mma2(const float* __restrict__ A, const float* __restrict__ W,
                  float* __restrict__ C, int M, int N, int K) {
    extern __shared__ float sm[];
    const int m0 = blockIdx.y * 128;
    const int n0 = blockIdx.x * 64;
    const int tid = threadIdx.x;
    const int wid = tid >> 5, lane = tid & 31;
    const int lr = lane >> 2, lc = lane & 3;
    const int wm = (wid >> 1) * 32;
    const int wn = (wid & 1) * 32;

    const uint32_t smem_base = (uint32_t)__cvta_generic_to_shared(sm);

    float acc[2][4][4] = {};
    const int kt = K / 32;

    {
        uint32_t As_u = smem_base;
        uint32_t Ws_u = smem_base + 128 * GST * 4;
#pragma unroll
        for (int t = 0; t < 4; t++) {
            int s = tid + t * 256;
            int r = s >> 3, c = (s & 7) * 4;
            cp_async16(As_u + (r * GST + c) * 4, A + (size_t)(m0 + r) * K + c);
        }
#pragma unroll
        for (int t = 0; t < 2; t++) {
            int s = tid + t * 256;
            int r = s >> 3, c = (s & 7) * 4;
            cp_async16(Ws_u + (r * GST + c) * 4, W + (size_t)(n0 + r) * K + c);
        }
    }
    cp_commit();

    for (int it = 0; it < kt; it++) {
        if (it + 1 < kt) {
            int k0 = (it + 1) * 32;
            uint32_t st = smem_base + ((it + 1) & 1) * PROJ_STAGE * 4;
            uint32_t As_u = st;
            uint32_t Ws_u = st + 128 * GST * 4;
#pragma unroll
            for (int t = 0; t < 4; t++) {
                int s = tid + t * 256;
                int r = s >> 3, c = (s & 7) * 4;
                cp_async16(As_u + (r * GST + c) * 4, A + (size_t)(m0 + r) * K + k0 + c);
            }
#pragma unroll
            for (int t = 0; t < 2; t++) {
                int s = tid + t * 256;
                int r = s >> 3, c = (s & 7) * 4;
                cp_async16(Ws_u + (r * GST + c) * 4, W + (size_t)(n0 + r) * K + k0 + c);
            }
        }
        cp_commit();
        cp_wait1();
        __syncthreads();

        const float* As = sm + (it & 1) * PROJ_STAGE;
        const float* Ws = As + 128 * GST;
#pragma unroll
        for (int kk = 0; kk < 32; kk += 8) {
            uint32_t a[2][4], b[4][2];
#pragma unroll
            for (int mi = 0; mi < 2; mi++) {
                int r0 = wm + mi * 16 + lr;
                a[mi][0] = f2tf32(As[r0 * GST + kk + lc]);
                a[mi][1] = f2tf32(As[(r0 + 8) * GST + kk + lc]);
                a[mi][2] = f2tf32(As[r0 * GST + kk + lc + 4]);
                a[mi][3] = f2tf32(As[(r0 + 8) * GST + kk + lc + 4]);
            }
#pragma unroll
            for (int nj = 0; nj < 4; nj++) {
                int rn = wn + nj * 8 + lr;
                b[nj][0] = f2tf32(Ws[rn * GST + kk + lc]);
                b[nj][1] = f2tf32(Ws[rn * GST + kk + lc + 4]);
            }
#pragma unroll
            for (int mi = 0; mi < 2; mi++)
#pragma unroll
                for (int nj = 0; nj < 4; nj++)
                    mma_tf32(acc[mi][nj], a[mi], b[nj], acc[mi][nj]);
        }
        __syncthreads();
    }

#pragma unroll
    for (int mi = 0; mi < 2; mi++) {
        int row = m0 + wm + mi * 16 + lr;
#pragma unroll
        for (int nj = 0; nj < 4; nj++) {
            int col = n0 + wn + nj * 8 + 2 * lc;
            *(float2*)(C + (size_t)row * N + col) =
                make_float2(acc[mi][nj][0], acc[mi][nj][1]);
            *(float2*)(C + (size_t)(row + 8) * N + col) =
                make_float2(acc[mi][nj][2], acc[mi][nj][3]);
        }
    }
}

// ---------------------------------------------------------------------------
// Pipelined batched MMA GEMM-NN: C_b[M,N] = A_b[M,K] * B_b[K,N], tf32.
// ---------------------------------------------------------------------------
#define NNST_A 36
#define NNST_B 72
#define NN_STAGE (64 * NNST_A + 32 * NNST_B)

__global__ __launch_bounds__(256, 2)
void gemm_nn_mma(const float* __restrict__ A, const float* __restrict__ B,
                 float* __restrict__ C, int M, int N, int K,
                 size_t strideA, size_t strideB, size_t strideC) {
    __shared__ float sm[2 * NN_STAGE];
    const float* Ab = A + (size_t)blockIdx.z * strideA;
    const float* Bb = B + (size_t)blockIdx.z * strideB;
    float* Cb = C + (size_t)blockIdx.z * strideC;
    const int m0 = blockIdx.y * 64;
    const int n0 = blockIdx.x * 64;
    const int tid = threadIdx.x;
    const int wid = tid >> 5, lane = tid & 31;
    const int lr = lane >> 2, lc = lane & 3;
    const int wm = (wid >> 1) * 16;
    const int wn = (wid & 1) * 32;

    const uint32_t smem_base = (uint32_t)__cvta_generic_to_shared(sm);
    float acc[4][4] = {};
    const int kt = K / 32;

    {
        uint32_t As_u = smem_base;
        uint32_t Bs_u = smem_base + 64 * NNST_A * 4;
#pragma unroll
        for (int t = 0; t < 2; t++) {
            int s = tid + t * 256;
            int r = s >> 3, c = (s & 7) * 4;
            cp_async16(As_u + (r * NNST_A + c) * 4, Ab + (size_t)(m0 + r) * K + c);
        }
#pragma unroll
        for (int t = 0; t < 2; t++) {
            int s = tid + t * 256;
            int r = s >> 4, c = (s & 15) * 4;
            cp_async16(Bs_u + (r * NNST_B + c) * 4, Bb + (size_t)r * N + n0 + c);
        }
    }
    cp_commit();

    for (int it = 0; it < kt; it++) {
        if (it + 1 < kt) {
            int k0 = (it + 1) * 32;
            uint32_t st = smem_base + ((it + 1) & 1) * NN_STAGE * 4;
            uint32_t As_u = st;
            uint32_t Bs_u = st + 64 * NNST_A * 4;
#pragma unroll
            for (int t = 0; t < 2; t++) {
                int s = tid + t * 256;
                int r = s >> 3, c = (s & 7) * 4;
                cp_async16(As_u + (r * NNST_A + c) * 4, Ab + (size_t)(m0 + r) * K + k0 + c);
            }
#pragma unroll
            for (int t = 0; t < 2; t++) {
                int s = tid + t * 256;
                int r = s >> 4, c = (s & 15) * 4;
                cp_async16(Bs_u + (r * NNST_B + c) * 4, Bb + (size_t)(k0 + r) * N + n0 + c);
            }
        }
        cp_commit();
        cp_wait1();
        __syncthreads();

        const float* As = sm + (it & 1) * NN_STAGE;
        const float* Bs = As + 64 * NNST_A;
#pragma unroll
        for (int kk = 0; kk < 32; kk += 8) {
            uint32_t a[4], b[4][2];
            int r0 = wm + lr;
            a[0] = f2tf32(As[r0 * NNST_A + kk + lc]);
            a[1] = f2tf32(As[(r0 + 8) * NNST_A + kk + lc]);
            a[2] = f2tf32(As[r0 * NNST_A + kk + lc + 4]);
            a[3] = f2tf32(As[(r0 + 8) * NNST_A + kk + lc + 4]);
#pragma unroll
            for (int nj = 0; nj < 4; nj++) {
                int rn = wn + nj * 8 + lr;
                b[nj][0] = f2tf32(Bs[(kk + lc) * NNST_B + rn]);
                b[nj][1] = f2tf32(Bs[(kk + lc + 4) * NNST_B + rn]);
            }
#pragma unroll
            for (int nj = 0; nj < 4; nj++)
                mma_tf32(acc[nj], a, b[nj], acc[nj]);
        }
        __syncthreads();
    }

    {
        int row = m0 + wm + lr;
#pragma unroll
        for (int nj = 0; nj < 4; nj++) {
            int col = n0 + wn + nj * 8 + 2 * lc;
            *(float2*)(Cb + (size_t)row * N + col) =
                make_float2(acc[nj][0], acc[nj][1]);
            *(float2*)(Cb + (size_t)(row + 8) * N + col) =
                make_float2(acc[nj][2], acc[nj][3]);
        }
    }
}

// ---------------------------------------------------------------------------
// Pass 1: row sums of exp(score). Block = (128 q rows, h, b), 8 warps,
// warp tile 32q x 64k. K chunks double-buffered via cp.async; smem raw fp32,
// tf32 cvt at fragment load; 1/sqrt(dk) applied post-MMA.
// ---------------------------------------------------------------------------
#define QST 68
#define KCH_F (128 * QST)
#define SUMS_SMEM ((128 * QST + 2 * KCH_F) * 4)

__global__ __launch_bounds__(256, 2)
void attn_sums_kernel(const float* __restrict__ qh,
                      const float* __restrict__ kh,
                      float* __restrict__ rsuminv) {
    extern __shared__ float smf[];
    float* qs = smf;
    float* ks = smf + 128 * QST;
    __shared__ float ssum[2][128];

    const int q0 = blockIdx.x * 128;
    const int h = blockIdx.y;
    const int b = blockIdx.z;
    const int tid = threadIdx.x;
    const int wid = tid >> 5, lane = tid & 31;
    const int lr = lane >> 2, lc = lane & 3;
    const int wq = wid >> 1, wk = wid & 1;

    const uint32_t qs_u = (uint32_t)__cvta_generic_to_shared(qs);
    const uint32_t ks_u = (uint32_t)__cvta_generic_to_shared(ks);

    const float* qbase = qh + ((size_t)(b * SS + q0)) * DD + h * DK;
    const float* kbase = kh + ((size_t)b * SS) * DD + h * DK;

    {
#pragma unroll
        for (int t = 0; t < 8; t++) {
            int s = tid + t * 256;
            int r = s >> 4, c4 = (s & 15) * 4;
            cp_async16(qs_u + (r * QST + c4) * 4, qbase + (size_t)r * DD + c4);
        }
#pragma unroll
        for (int t = 0; t < 8; t++) {
            int s = tid + t * 256;
            int r = s >> 4, c4 = (s & 15) * 4;
            cp_async16(ks_u + (r * QST + c4) * 4, kbase + (size_t)r * DD + c4);
        }
    }
    cp_commit();

    float rs[2][2] = {};

    for (int ck = 0; ck < SS / 128; ck++) {
        if (ck + 1 < SS / 128) {
            uint32_t dst = ks_u + ((ck + 1) & 1) * KCH_F * 4;
            const float* src = kbase + (size_t)(ck + 1) * 128 * DD;
#pragma unroll
            for (int t = 0; t < 8; t++) {
                int s = tid + t * 256;
                int r = s >> 4, c4 = (s & 15) * 4;
                cp_async16(dst + (r * QST + c4) * 4, src + (size_t)r * DD + c4);
            }
        }
        cp_commit();
        cp_wait1();
        __syncthreads();

        const float* kst = ks + (ck & 1) * KCH_F;

        float acc[2][8][4] = {};
#pragma unroll
        for (int kk = 0; kk < DK; kk += 8) {
            uint32_t a[2][4];
#pragma unroll
            for (int mi = 0; mi < 2; mi++) {
                int r0 = wq * 32 + mi * 16 + lr;
                a[mi][0] = f2tf32(qs[r0 * QST + kk + lc]);
                a[mi][1] = f2tf32(qs[(r0 + 8) * QST + kk + lc]);
                a[mi][2] = f2tf32(qs[r0 * QST + kk + lc + 4]);
                a[mi][3] = f2tf32(qs[(r0 + 8) * QST + kk + lc + 4]);
            }
#pragma unroll
            for (int nj = 0; nj < 8; nj++) {
                int rn = wk * 64 + nj * 8 + lr;
                uint32_t bf[2];
                bf[0] = f2tf32(kst[rn * QST + kk + lc]);
                bf[1] = f2tf32(kst[rn * QST + kk + lc + 4]);
                mma_tf32(acc[0][nj], a[0], bf, acc[0][nj]);
                mma_tf32(acc[1][nj], a[1], bf, acc[1][nj]);
            }
        }
#pragma unroll
        for (int mi = 0; mi < 2; mi++)
#pragma unroll
            for (int nj = 0; nj < 8; nj++) {
                rs[mi][0] += __expf(acc[mi][nj][0] * 0.125f) + __expf(acc[mi][nj][1] * 0.125f);
                rs[mi][1] += __expf(acc[mi][nj][2] * 0.125f) + __expf(acc[mi][nj][3] * 0.125f);
            }
        __syncthreads();
    }
#pragma unroll
    for (int off = 1; off <= 2; off <<= 1) {
#pragma unroll
        for (int mi = 0; mi < 2; mi++) {
            rs[mi][0] += __shfl_xor_sync(0xffffffffu, rs[mi][0], off);
            rs[mi][1] += __shfl_xor_sync(0xffffffffu, rs[mi][1], off);
        }
    }
    if (lc == 0) {
#pragma unroll
        for (int mi = 0; mi < 2; mi++) {
            ssum[wk][wq * 32 + mi * 16 + lr] = rs[mi][0];
            ssum[wk][wq * 32 + mi * 16 + lr + 8] = rs[mi][1];
        }
    }
    __syncthreads();
    if (tid < 128)
        rsuminv[(size_t)(h * NB + b) * SS + q0 + tid] =
            1.f / (ssum[0][tid] + ssum[1][tid]);
}

// ---------------------------------------------------------------------------
// Pass 2: per head, recompute scores, write normalized attn, accumulate
// P_avg in registers; heads double-buffered via cp.async.
// Block = (64 q rows, one 128-key chunk, b); 8 warps, warp tile 16q x 64k.
// ---------------------------------------------------------------------------
#define WR_STAGE (192 * QST)
#define WRITE_SMEM (2 * WR_STAGE * 4)

__global__ __launch_bounds__(256, 2)
void attn_write_kernel(const float* __restrict__ qh,
                       const float* __restrict__ kh,
                       const float* __restrict__ rsuminv,
                       float* __restrict__ attn_out,
                       float* __restrict__ pavg) {
    extern __shared__ float smf[];

    const int q0 = blockIdx.x * 64;
    const int ck = blockIdx.y;
    const int b = blockIdx.z;
    const int kb = ck * 128;
    const int tid = threadIdx.x;
    const int wid = tid >> 5, lane = tid & 31;
    const int lr = lane >> 2, lc = lane & 3;
    const int wq = wid >> 1, wk = wid & 1;
    const int r0l = wq * 16 + lr;

    const uint32_t smem_base = (uint32_t)__cvta_generic_to_shared(smf);

    const float* qb0 = qh + ((size_t)(b * SS + q0)) * DD;
    const float* kb0 = kh + ((size_t)(b * SS + kb)) * DD;

    {
        uint32_t qd = smem_base;
        uint32_t kd = smem_base + 64 * QST * 4;
#pragma unroll
        for (int t = 0; t < 4; t++) {
            int s = tid + t * 256;
            int r = s >> 4, c4 = (s & 15) * 4;
            cp_async16(qd + (r * QST + c4) * 4, qb0 + (size_t)r * DD + c4);
        }
#pragma unroll
        for (int t = 0; t < 8; t++) {
            int s = tid + t * 256;
            int r = s >> 4, c4 = (s & 15) * 4;
            cp_async16(kd + (r * QST + c4) * 4, kb0 + (size_t)r * DD + c4);
        }
    }
    cp_commit();

    float pav[8][4] = {};

    for (int h = 0; h < NH; h++) {
        if (h + 1 < NH) {
            uint32_t st = smem_base + ((h + 1) & 1) * WR_STAGE * 4;
            uint32_t qd = st;
            uint32_t kd = st + 64 * QST * 4;
            const float* qsrc = qb0 + (h + 1) * DK;
            const float* ksrc = kb0 + (h + 1) * DK;
#pragma unroll
            for (int t = 0; t < 4; t++) {
                int s = tid + t * 256;
                int r = s >> 4, c4 = (s & 15) * 4;
                cp_async16(qd + (r * QST + c4) * 4, qsrc + (size_t)r * DD + c4);
            }
#pragma unroll
            for (int t = 0; t < 8; t++) {
                int s = tid + t * 256;
                int r = s >> 4, c4 = (s & 15) * 4;
                cp_async16(kd + (r * QST + c4) * 4, ksrc + (size_t)r * DD + c4);
            }
        }
        cp_commit();
        cp_wait1();
        __syncthreads();

        const float* qs = smf + (h & 1) * WR_STAGE;
        const float* ks = qs + 64 * QST;

        float acc[8][4] = {};
#pragma unroll
        for (int kk = 0; kk < DK; kk += 8) {
            uint32_t a[4];
            a[0] = f2tf32(qs[r0l * QST + kk + lc]);
            a[1] = f2tf32(qs[(r0l + 8) * QST + kk + lc]);
            a[2] = f2tf32(qs[r0l * QST + kk + lc + 4]);
            a[3] = f2tf32(qs[(r0l + 8) * QST + kk + lc + 4]);
#pragma unroll
            for (int nj = 0; nj < 8; nj++) {
                int rn = wk * 64 + nj * 8 + lr;
                uint32_t bf[2];
                bf[0] = f2tf32(ks[rn * QST + kk + lc]);
                bf[1] = f2tf32(ks[rn * QST + kk + lc + 4]);
                mma_tf32(acc[nj], a, bf, acc[nj]);
            }
        }

        const float inv0 = rsuminv[(size_t)(h * NB + b) * SS + q0 + r0l];
        const float inv1 = rsuminv[(size_t)(h * NB + b) * SS + q0 + r0l + 8];
        float* orow0 = attn_out + (((size_t)(h * NB + b) * SS) + q0 + r0l) * SS + kb;
        float* orow1 = orow0 + (size_t)8 * SS;
#pragma unroll
        for (int nj = 0; nj < 8; nj++) {
            int col = wk * 64 + nj * 8 + 2 * lc;
            float e0 = __expf(acc[nj][0] * 0.125f) * inv0;
            float e1 = __expf(acc[nj][1] * 0.125f) * inv0;
            float e2 = __expf(acc[nj][2] * 0.125f) * inv1;
            float e3 = __expf(acc[nj][3] * 0.125f) * inv1;
            *(float2*)(orow0 + col) = make_float2(e0, e1);
            *(float2*)(orow1 + col) = make_float2(e2, e3);
            pav[nj][0] += e0; pav[nj][1] += e1;
            pav[nj][2] += e2; pav[nj][3] += e3;
        }
        __syncthreads();
    }

    float* prow0 = pavg + ((size_t)b * SS + q0 + r0l) * SS + kb;
    float* prow1 = prow0 + (size_t)8 * SS;
#pragma unroll
    for (int nj = 0; nj < 8; nj++) {
        int col = wk * 64 + nj * 8 + 2 * lc;
        *(float2*)(prow0 + col) = make_float2(pav[nj][0] * 0.125f, pav[nj][1] * 0.125f);
        *(float2*)(prow1 + col) = make_float2(pav[nj][2] * 0.125f, pav[nj][3] * 0.125f);
    }
}

// ---------------------------------------------------------------------------
extern "C" void kernel_launch(void* const* d_in, const int* in_sizes, int n_in,
                              void* d_out, int out_size) {
    const float* q  = (const float*)d_in[0];
    const float* k  = (const float*)d_in[1];
    const float* v  = (const float*)d_in[2];
    const float* Wq = (const float*)d_in[3];
    const float* Wk = (const float*)d_in[4];
    const float* Wv = (const float*)d_in[5];
    const float* Wo = (const float*)d_in[6];
    float* out  = (float*)d_out;
    float* attn = out + OUT_ELEMS;

    float *qh, *kh, *vs, *pavg, *head, *rsuminv;
    cudaGetSymbolAddress((void**)&qh,      g_qh);
    cudaGetSymbolAddress((void**)&kh,      g_kh);
    cudaGetSymbolAddress((void**)&vs,      g_vs);
    cudaGetSymbolAddress((void**)&pavg,    g_pavg);
    cudaGetSymbolAddress((void**)&head,    g_head);
    cudaGetSymbolAddress((void**)&rsuminv, g_rsuminv);

    cudaFuncSetAttribute(gemm_nt_mma2,
                         cudaFuncAttributeMaxDynamicSharedMemorySize, PROJ_SMEM);
    cudaFuncSetAttribute(attn_sums_kernel,
                         cudaFuncAttributeMaxDynamicSharedMemorySize, SUMS_SMEM);
    cudaFuncSetAttribute(attn_write_kernel,
                         cudaFuncAttributeMaxDynamicSharedMemorySize, WRITE_SMEM);

    gemm_nt_mma2<<<dim3(DD / 64, MROWS / 128), 256, PROJ_SMEM>>>(q, Wq, qh, MROWS, DD, DD);
    gemm_nt_mma2<<<dim3(DD / 64, MROWS / 128), 256, PROJ_SMEM>>>(k, Wk, kh, MROWS, DD, DD);
    gemm_nt_mma2<<<dim3(DK / 64, MROWS / 128), 256, PROJ_SMEM>>>(v, Wv, vs, MROWS, DK, DD);

    attn_sums_kernel<<<dim3(SS / 128, NH, NB), 256, SUMS_SMEM>>>(qh, kh, rsuminv);

    attn_write_kernel<<<dim3(SS / 64, SS / 128, NB), 256, WRITE_SMEM>>>(
        qh, kh, rsuminv, attn, pavg);

    gemm_nn_mma<<<dim3(1, SS / 64, NB), 256>>>(
        pavg, vs, head, SS, DK, SS,
        (size_t)SS * SS, (size_t)SS * DK, (size_t)SS * DK);

    gemm_nt_mma2<<<dim3(DD / 64, MROWS / 128), 256, PROJ_SMEM>>>(head, Wo, out, MROWS, DD, DK);
}

// round 14
// speedup vs baseline: 1.0537x; 1.0537x over previous
// Round 14.
//
// Post-mortem R13: cp.async pipelining REGRESSED attn_sums 62.6->74.6us
// (total 313->324). The profile says why: alu pipe jumped 11.8% -> 28.7%
// and issue 39->57% while tensor FELL 43.7->37.7. Moving f2tf32 from the
// smem-fill (one cvt per element) to the fragment-load path multiplied the
// conversions: each K element is fragment-loaded by 4 warps and each Q
// element by 2, so the kernel became instruction-bound on CVT. The
// pipelining itself was fine; the conversion placement was the bug.
//
// Fix (this round): make the PROJECTION GEMMs emit qh/kh/vs already
// tf32-rounded (one cvt per output element in the epilogue, ~free). Then
// the attention kernels cp.async raw bits that are ALREADY tf32: fragment
// loads become plain LDS reinterprets -- zero cvt instructions in the hot
// loops -- while keeping the double-buffered DMA. Numerics are identical
// to round 7 (same single rna-cvt per value; 0.125 scale is an exact
// power of two applied post-MMA). Final out projection keeps full fp32
// output (cvt_out=0).
//
// Prediction: attn_sums 74.6 -> ~45us (alu -> <10%, tensor -> ~55%+),
// attn_write ~120 -> ~90us, total 324 -> ~260-275us, rel_err ~5e-4
// unchanged. If attn_write stays >100us it is store-bandwidth bound and
// the next lever is fusing the pavg@vs split-K into pass 2.

#include <cuda_runtime.h>
#include <cuda_bf16.h>
#include <math.h>
#include <stdint.h>

#define NB 8
#define SS 1024
#define DD 512
#define NH 8
#define DK 64
#define MROWS (NB * SS)
#define OUT_ELEMS (NB * SS * DD)

__device__ float g_qh[MROWS * DD];
__device__ float g_kh[MROWS * DD];
__device__ float g_vs[MROWS * DK];
__device__ float g_pavg[NB * SS * SS];
__device__ float g_head[MROWS * DK];
__device__ float g_rsuminv[NH * NB * SS];

__device__ __forceinline__ uint32_t f2tf32(float x) {
    uint32_t r;
    asm("cvt.rna.tf32.f32 %0, %1;" : "=r"(r) : "f"(x));
    return r;
}

__device__ __forceinline__ void mma_tf32(float* d, const uint32_t* a,
                                         const uint32_t* b, const float* c) {
    asm volatile(
        "mma.sync.aligned.m16n8k8.row.col.f32.tf32.tf32.f32 "
        "{%0,%1,%2,%3}, {%4,%5,%6,%7}, {%8,%9}, {%10,%11,%12,%13};"
        : "=f"(d[0]), "=f"(d[1]), "=f"(d[2]), "=f"(d[3])
        : "r"(a[0]), "r"(a[1]), "r"(a[2]), "r"(a[3]),
          "r"(b[0]), "r"(b[1]),
          "f"(c[0]), "f"(c[1]), "f"(c[2]), "f"(c[3]));
}

__device__ __forceinline__ void cp_async16(uint32_t dst, const void* src) {
    asm volatile("cp.async.cg.shared.global [%0], [%1], 16;" :: "r"(dst), "l"(src));
}
__device__ __forceinline__ void cp_commit() {
    asm volatile("cp.async.commit_group;");
}
__device__ __forceinline__ void cp_wait1() {
    asm volatile("cp.async.wait_group 1;");
}

__device__ __forceinline__ float maybe_tf32(float x, int cvt) {
    return cvt ? __uint_as_float(f2tf32(x)) : x;
}

// ---------------------------------------------------------------------------
// Pipelined MMA GEMM-NT: C[M,N] = A[M,K] * W[N,K]^T, tf32.
// BM=128, BN=64, BK=32, 2-stage cp.async double buffer. 8 warps (4Mx2N).
// cvt_out!=0 => outputs are tf32-rounded (for downstream MMA consumers).
// ---------------------------------------------------------------------------
#define GST 36
#define PROJ_STAGE (192 * GST)
#define PROJ_SMEM (2 * PROJ_STAGE * 4)

__global__ __launch_bounds__(256, 2)
void gemm_nt_mma2(const float* __restrict__ A, const float* __restrict__ W,
                  float* __restrict__ C, int M, int N, int K, int cvt_out) {
    extern __shared__ float sm[];
    const int m0 = blockIdx.y * 128;
    const int n0 = blockIdx.x * 64;
    const int tid = threadIdx.x;
    const int wid = tid >> 5, lane = tid & 31;
    const int lr = lane >> 2, lc = lane & 3;
    const int wm = (wid >> 1) * 32;
    const int wn = (wid & 1) * 32;

    const uint32_t smem_base = (uint32_t)__cvta_generic_to_shared(sm);

    float acc[2][4][4] = {};
    const int kt = K / 32;

    {
        uint32_t As_u = smem_base;
        uint32_t Ws_u = smem_base + 128 * GST * 4;
#pragma unroll
        for (int t = 0; t < 4; t++) {
            int s = tid + t * 256;
            int r = s >> 3, c = (s & 7) * 4;
            cp_async16(As_u + (r * GST + c) * 4, A + (size_t)(m0 + r) * K + c);
        }
#pragma unroll
        for (int t = 0; t < 2; t++) {
            int s = tid + t * 256;
            int r = s >> 3, c = (s & 7) * 4;
            cp_async16(Ws_u + (r * GST + c) * 4, W + (size_t)(n0 + r) * K + c);
        }
    }
    cp_commit();

    for (int it = 0; it < kt; it++) {
        if (it + 1 < kt) {
            int k0 = (it + 1) * 32;
            uint32_t st = smem_base + ((it + 1) & 1) * PROJ_STAGE * 4;
            uint32_t As_u = st;
            uint32_t Ws_u = st + 128 * GST * 4;
#pragma unroll
            for (int t = 0; t < 4; t++) {
                int s = tid + t * 256;
                int r = s >> 3, c = (s & 7) * 4;
                cp_async16(As_u + (r * GST + c) * 4, A + (size_t)(m0 + r) * K + k0 + c);
            }
#pragma unroll
            for (int t = 0; t < 2; t++) {
                int s = tid + t * 256;
                int r = s >> 3, c = (s & 7) * 4;
                cp_async16(Ws_u + (r * GST + c) * 4, W + (size_t)(n0 + r) * K + k0 + c);
            }
        }
        cp_commit();
        cp_wait1();
        __syncthreads();

        const float* As = sm + (it & 1) * PROJ_STAGE;
        const float* Ws = As + 128 * GST;
#pragma unroll
        for (int kk = 0; kk < 32; kk += 8) {
            uint32_t a[2][4], b[4][2];
#pragma unroll
            for (int mi = 0; mi < 2; mi++) {
                int r0 = wm + mi * 16 + lr;
                a[mi][0] = f2tf32(As[r0 * GST + kk + lc]);
                a[mi][1] = f2tf32(As[(r0 + 8) * GST + kk + lc]);
                a[mi][2] = f2tf32(As[r0 * GST + kk + lc + 4]);
                a[mi][3] = f2tf32(As[(r0 + 8) * GST + kk + lc + 4]);
            }
#pragma unroll
            for (int nj = 0; nj < 4; nj++) {
                int rn = wn + nj * 8 + lr;
                b[nj][0] = f2tf32(Ws[rn * GST + kk + lc]);
                b[nj][1] = f2tf32(Ws[rn * GST + kk + lc + 4]);
            }
#pragma unroll
            for (int mi = 0; mi < 2; mi++)
#pragma unroll
                for (int nj = 0; nj < 4; nj++)
                    mma_tf32(acc[mi][nj], a[mi], b[nj], acc[mi][nj]);
        }
        __syncthreads();
    }

#pragma unroll
    for (int mi = 0; mi < 2; mi++) {
        int row = m0 + wm + mi * 16 + lr;
#pragma unroll
        for (int nj = 0; nj < 4; nj++) {
            int col = n0 + wn + nj * 8 + 2 * lc;
            *(float2*)(C + (size_t)row * N + col) =
                make_float2(maybe_tf32(acc[mi][nj][0], cvt_out),
                            maybe_tf32(acc[mi][nj][1], cvt_out));
            *(float2*)(C + (size_t)(row + 8) * N + col) =
                make_float2(maybe_tf32(acc[mi][nj][2], cvt_out),
                            maybe_tf32(acc[mi][nj][3], cvt_out));
        }
    }
}

// ---------------------------------------------------------------------------
// Pipelined batched MMA GEMM-NN: C_b[M,N] = A_b[M,K] * B_b[K,N], tf32.
// B (= vs) is already tf32-rounded; A (= pavg) converted per fragment.
// ---------------------------------------------------------------------------
#define NNST_A 36
#define NNST_B 72
#define NN_STAGE (64 * NNST_A + 32 * NNST_B)

__global__ __launch_bounds__(256, 2)
void gemm_nn_mma(const float* __restrict__ A, const float* __restrict__ B,
                 float* __restrict__ C, int M, int N, int K,
                 size_t strideA, size_t strideB, size_t strideC) {
    __shared__ float sm[2 * NN_STAGE];
    const float* Ab = A + (size_t)blockIdx.z * strideA;
    const float* Bb = B + (size_t)blockIdx.z * strideB;
    float* Cb = C + (size_t)blockIdx.z * strideC;
    const int m0 = blockIdx.y * 64;
    const int n0 = blockIdx.x * 64;
    const int tid = threadIdx.x;
    const int wid = tid >> 5, lane = tid & 31;
    const int lr = lane >> 2, lc = lane & 3;
    const int wm = (wid >> 1) * 16;
    const int wn = (wid & 1) * 32;

    const uint32_t smem_base = (uint32_t)__cvta_generic_to_shared(sm);
    float acc[4][4] = {};
    const int kt = K / 32;

    {
        uint32_t As_u = smem_base;
        uint32_t Bs_u = smem_base + 64 * NNST_A * 4;
#pragma unroll
        for (int t = 0; t < 2; t++) {
            int s = tid + t * 256;
            int r = s >> 3, c = (s & 7) * 4;
            cp_async16(As_u + (r * NNST_A + c) * 4, Ab + (size_t)(m0 + r) * K + c);
        }
#pragma unroll
        for (int t = 0; t < 2; t++) {
            int s = tid + t * 256;
            int r = s >> 4, c = (s & 15) * 4;
            cp_async16(Bs_u + (r * NNST_B + c) * 4, Bb + (size_t)r * N + n0 + c);
        }
    }
    cp_commit();

    for (int it = 0; it < kt; it++) {
        if (it + 1 < kt) {
            int k0 = (it + 1) * 32;
            uint32_t st = smem_base + ((it + 1) & 1) * NN_STAGE * 4;
            uint32_t As_u = st;
            uint32_t Bs_u = st + 64 * NNST_A * 4;
#pragma unroll
            for (int t = 0; t < 2; t++) {
                int s = tid + t * 256;
                int r = s >> 3, c = (s & 7) * 4;
                cp_async16(As_u + (r * NNST_A + c) * 4, Ab + (size_t)(m0 + r) * K + k0 + c);
            }
#pragma unroll
            for (int t = 0; t < 2; t++) {
                int s = tid + t * 256;
                int r = s >> 4, c = (s & 15) * 4;
                cp_async16(Bs_u + (r * NNST_B + c) * 4, Bb + (size_t)(k0 + r) * N + n0 + c);
            }
        }
        cp_commit();
        cp_wait1();
        __syncthreads();

        const float* As = sm + (it & 1) * NN_STAGE;
        const float* Bs = As + 64 * NNST_A;
#pragma unroll
        for (int kk = 0; kk < 32; kk += 8) {
            uint32_t a[4], b[4][2];
            int r0 = wm + lr;
            a[0] = f2tf32(As[r0 * NNST_A + kk + lc]);
            a[1] = f2tf32(As[(r0 + 8) * NNST_A + kk + lc]);
            a[2] = f2tf32(As[r0 * NNST_A + kk + lc + 4]);
            a[3] = f2tf32(As[(r0 + 8) * NNST_A + kk + lc + 4]);
#pragma unroll
            for (int nj = 0; nj < 4; nj++) {
                int rn = wn + nj * 8 + lr;
                b[nj][0] = __float_as_uint(Bs[(kk + lc) * NNST_B + rn]);
                b[nj][1] = __float_as_uint(Bs[(kk + lc + 4) * NNST_B + rn]);
            }
#pragma unroll
            for (int nj = 0; nj < 4; nj++)
                mma_tf32(acc[nj], a, b[nj], acc[nj]);
        }
        __syncthreads();
    }

    {
        int row = m0 + wm + lr;
#pragma unroll
        for (int nj = 0; nj < 4; nj++) {
            int col = n0 + wn + nj * 8 + 2 * lc;
            *(float2*)(Cb + (size_t)row * N + col) =
                make_float2(acc[nj][0], acc[nj][1]);
            *(float2*)(Cb + (size_t)(row + 8) * N + col) =
                make_float2(acc[nj][2], acc[nj][3]);
        }
    }
}

// ---------------------------------------------------------------------------
// Pass 1: row sums of exp(score). Block = (128 q rows, h, b), 8 warps,
// warp tile 32q x 64k. K chunks double-buffered via cp.async. qh/kh are
// pre-rounded tf32 -> fragment loads are plain LDS (no cvt in hot loop).
// 1/sqrt(dk) applied post-MMA.
// ---------------------------------------------------------------------------
#define QST 68
#define KCH_F (128 * QST)
#define SUMS_SMEM ((128 * QST + 2 * KCH_F) * 4)

__global__ __launch_bounds__(256, 2)
void attn_sums_kernel(const float* __restrict__ qh,
                      const float* __restrict__ kh,
                      float* __restrict__ rsuminv) {
    extern __shared__ float smf[];
    const float* qs = smf;
    const float* ks = smf + 128 * QST;
    __shared__ float ssum[2][128];

    const int q0 = blockIdx.x * 128;
    const int h = blockIdx.y;
    const int b = blockIdx.z;
    const int tid = threadIdx.x;
    const int wid = tid >> 5, lane = tid & 31;
    const int lr = lane >> 2, lc = lane & 3;
    const int wq = wid >> 1, wk = wid & 1;

    const uint32_t qs_u = (uint32_t)__cvta_generic_to_shared(smf);
    const uint32_t ks_u = qs_u + 128 * QST * 4;

    const float* qbase = qh + ((size_t)(b * SS + q0)) * DD + h * DK;
    const float* kbase = kh + ((size_t)b * SS) * DD + h * DK;

    {
#pragma unroll
        for (int t = 0; t < 8; t++) {
            int s = tid + t * 256;
            int r = s >> 4, c4 = (s & 15) * 4;
            cp_async16(qs_u + (r * QST + c4) * 4, qbase + (size_t)r * DD + c4);
        }
#pragma unroll
        for (int t = 0; t < 8; t++) {
            int s = tid + t * 256;
            int r = s >> 4, c4 = (s & 15) * 4;
            cp_async16(ks_u + (r * QST + c4) * 4, kbase + (size_t)r * DD + c4);
        }
    }
    cp_commit();

    float rs[2][2] = {};

    for (int ck = 0; ck < SS / 128; ck++) {
        if (ck + 1 < SS / 128) {
            uint32_t dst = ks_u + ((ck + 1) & 1) * KCH_F * 4;
            const float* src = kbase + (size_t)(ck + 1) * 128 * DD;
#pragma unroll
            for (int t = 0; t < 8; t++) {
                int s = tid + t * 256;
                int r = s >> 4, c4 = (s & 15) * 4;
                cp_async16(dst + (r * QST + c4) * 4, src + (size_t)r * DD + c4);
            }
        }
        cp_commit();
        cp_wait1();
        __syncthreads();

        const float* kst = ks + (ck & 1) * KCH_F;

        float acc[2][8][4] = {};
#pragma unroll
        for (int kk = 0; kk < DK; kk += 8) {
            uint32_t a[2][4];
#pragma unroll
            for (int mi = 0; mi < 2; mi++) {
                int r0 = wq * 32 + mi * 16 + lr;
                a[mi][0] = __float_as_uint(qs[r0 * QST + kk + lc]);
                a[mi][1] = __float_as_uint(qs[(r0 + 8) * QST + kk + lc]);
                a[mi][2] = __float_as_uint(qs[r0 * QST + kk + lc + 4]);
                a[mi][3] = __float_as_uint(qs[(r0 + 8) * QST + kk + lc + 4]);
            }
#pragma unroll
            for (int nj = 0; nj < 8; nj++) {
                int rn = wk * 64 + nj * 8 + lr;
                uint32_t bf[2];
                bf[0] = __float_as_uint(kst[rn * QST + kk + lc]);
                bf[1] = __float_as_uint(kst[rn * QST + kk + lc + 4]);
                mma_tf32(acc[0][nj], a[0], bf, acc[0][nj]);
                mma_tf32(acc[1][nj], a[1], bf, acc[1][nj]);
            }
        }
#pragma unroll
        for (int mi = 0; mi < 2; mi++)
#pragma unroll
            for (int nj = 0; nj < 8; nj++) {
                rs[mi][0] += __expf(acc[mi][nj][0] * 0.125f) + __expf(acc[mi][nj][1] * 0.125f);
                rs[mi][1] += __expf(acc[mi][nj][2] * 0.125f) + __expf(acc[mi][nj][3] * 0.125f);
            }
        __syncthreads();
    }
#pragma unroll
    for (int off = 1; off <= 2; off <<= 1) {
#pragma unroll
        for (int mi = 0; mi < 2; mi++) {
            rs[mi][0] += __shfl_xor_sync(0xffffffffu, rs[mi][0], off);
            rs[mi][1] += __shfl_xor_sync(0xffffffffu, rs[mi][1], off);
        }
    }
    if (lc == 0) {
#pragma unroll
        for (int mi = 0; mi < 2; mi++) {
            ssum[wk][wq * 32 + mi * 16 + lr] = rs[mi][0];
            ssum[wk][wq * 32 + mi * 16 + lr + 8] = rs[mi][1];
        }
    }
    __syncthreads();
    if (tid < 128)
        rsuminv[(size_t)(h * NB + b) * SS + q0 + tid] =
            1.f / (ssum[0][tid] + ssum[1][tid]);
}

// ---------------------------------------------------------------------------
// Pass 2: per head, recompute scores, write normalized attn, accumulate
// P_avg in registers; heads double-buffered via cp.async. No cvts.
// Block = (64 q rows, one 128-key chunk, b); 8 warps, warp tile 16q x 64k.
// ---------------------------------------------------------------------------
#define WR_STAGE (192 * QST)
#define WRITE_SMEM (2 * WR_STAGE * 4)

__global__ __launch_bounds__(256, 2)
void attn_write_kernel(const float* __restrict__ qh,
                       const float* __restrict__ kh,
                       const float* __restrict__ rsuminv,
                       float* __restrict__ attn_out,
                       float* __restrict__ pavg) {
    extern __shared__ float smf[];

    const int q0 = blockIdx.x * 64;
    const int ck = blockIdx.y;
    const int b = blockIdx.z;
    const int kb = ck * 128;
    const int tid = threadIdx.x;
    const int wid = tid >> 5, lane = tid & 31;
    const int lr = lane >> 2, lc = lane & 3;
    const int wq = wid >> 1, wk = wid & 1;
    const int r0l = wq * 16 + lr;

    const uint32_t smem_base = (uint32_t)__cvta_generic_to_shared(smf);

    const float* qb0 = qh + ((size_t)(b * SS + q0)) * DD;
    const float* kb0 = kh + ((size_t)(b * SS + kb)) * DD;

    {
        uint32_t qd = smem_base;
        uint32_t kd = smem_base + 64 * QST * 4;
#pragma unroll
        for (int t = 0; t < 4; t++) {
            int s = tid + t * 256;
            int r = s >> 4, c4 = (s & 15) * 4;
            cp_async16(qd + (r * QST + c4) * 4, qb0 + (size_t)r * DD + c4);
        }
#pragma unroll
        for (int t = 0; t < 8; t++) {
            int s = tid + t * 256;
            int r = s >> 4, c4 = (s & 15) * 4;
            cp_async16(kd + (r * QST + c4) * 4, kb0 + (size_t)r * DD + c4);
        }
    }
    cp_commit();

    float pav[8][4] = {};

    for (int h = 0; h < NH; h++) {
        if (h + 1 < NH) {
            uint32_t st = smem_base + ((h + 1) & 1) * WR_STAGE * 4;
            uint32_t qd = st;
            uint32_t kd = st + 64 * QST * 4;
            const float* qsrc = qb0 + (h + 1) * DK;
            const float* ksrc = kb0 + (h + 1) * DK;
#pragma unroll
            for (int t = 0; t < 4; t++) {
                int s = tid + t * 256;
                int r = s >> 4, c4 = (s & 15) * 4;
                cp_async16(qd + (r * QST + c4) * 4, qsrc + (size_t)r * DD + c4);
            }
#pragma unroll
            for (int t = 0; t < 8; t++) {
                int s = tid + t * 256;
                int r = s >> 4, c4 = (s & 15) * 4;
                cp_async16(kd + (r * QST + c4) * 4, ksrc + (size_t)r * DD + c4);
            }
        }
        cp_commit();
        cp_wait1();
        __syncthreads();

        const float* qs = smf + (h & 1) * WR_STAGE;
        const float* ks = qs + 64 * QST;

        float acc[8][4] = {};
#pragma unroll
        for (int kk = 0; kk < DK; kk += 8) {
            uint32_t a[4];
            a[0] = __float_as_uint(qs[r0l * QST + kk + lc]);
            a[1] = __float_as_uint(qs[(r0l + 8) * QST + kk + lc]);
            a[2] = __float_as_uint(qs[r0l * QST + kk + lc + 4]);
            a[3] = __float_as_uint(qs[(r0l + 8) * QST + kk + lc + 4]);
#pragma unroll
            for (int nj = 0; nj < 8; nj++) {
                int rn = wk * 64 + nj * 8 + lr;
                uint32_t bf[2];
                bf[0] = __float_as_uint(ks[rn * QST + kk + lc]);
                bf[1] = __float_as_uint(ks[rn * QST + kk + lc + 4]);
                mma_tf32(acc[nj], a, bf, acc[nj]);
            }
        }

        const float inv0 = rsuminv[(size_t)(h * NB + b) * SS + q0 + r0l];
        const float inv1 = rsuminv[(size_t)(h * NB + b) * SS + q0 + r0l + 8];
        float* orow0 = attn_out + (((size_t)(h * NB + b) * SS) + q0 + r0l) * SS + kb;
        float* orow1 = orow0 + (size_t)8 * SS;
#pragma unroll
        for (int nj = 0; nj < 8; nj++) {
            int col = wk * 64 + nj * 8 + 2 * lc;
            float e0 = __expf(acc[nj][0] * 0.125f) * inv0;
            float e1 = __expf(acc[nj][1] * 0.125f) * inv0;
            float e2 = __expf(acc[nj][2] * 0.125f) * inv1;
            float e3 = __expf(acc[nj][3] * 0.125f) * inv1;
            *(float2*)(orow0 + col) = make_float2(e0, e1);
            *(float2*)(orow1 + col) = make_float2(e2, e3);
            pav[nj][0] += e0; pav[nj][1] += e1;
            pav[nj][2] += e2; pav[nj][3] += e3;
        }
        __syncthreads();
    }

    float* prow0 = pavg + ((size_t)b * SS + q0 + r0l) * SS + kb;
    float* prow1 = prow0 + (size_t)8 * SS;
#pragma unroll
    for (int nj = 0; nj < 8; nj++) {
        int col = wk * 64 + nj * 8 + 2 * lc;
        *(float2*)(prow0 + col) = make_float2(pav[nj][0] * 0.125f, pav[nj][1] * 0.125f);
        *(float2*)(prow1 + col) = make_float2(pav[nj][2] * 0.125f, pav[nj][3] * 0.125f);
    }
}

// ---------------------------------------------------------------------------
extern "C" void kernel_launch(void* const* d_in, const int* in_sizes, int n_in,
                              void* d_out, int out_size) {
    const float* q  = (const float*)d_in[0];
    const float* k  = (const float*)d_in[1];
    const float* v  = (const float*)d_in[2];
    const float* Wq = (const float*)d_in[3];
    const float* Wk = (const float*)d_in[4];
    const float* Wv = (const float*)d_in[5];
    const float* Wo = (const float*)d_in[6];
    float* out  = (float*)d_out;
    float* attn = out + OUT_ELEMS;

    float *qh, *kh, *vs, *pavg, *head, *rsuminv;
    cudaGetSymbolAddress((void**)&qh,      g_qh);
    cudaGetSymbolAddress((void**)&kh,      g_kh);
    cudaGetSymbolAddress((void**)&vs,      g_vs);
    cudaGetSymbolAddress((void**)&pavg,    g_pavg);
    cudaGetSymbolAddress((void**)&head,    g_head);
    cudaGetSymbolAddress((void**)&rsuminv, g_rsuminv);

    cudaFuncSetAttribute(gemm_nt_mma2,
                         cudaFuncAttributeMaxDynamicSharedMemorySize, PROJ_SMEM);
    cudaFuncSetAttribute(attn_sums_kernel,
                         cudaFuncAttributeMaxDynamicSharedMemorySize, SUMS_SMEM);
    cudaFuncSetAttribute(attn_write_kernel,
                         cudaFuncAttributeMaxDynamicSharedMemorySize, WRITE_SMEM);

    // Projections; qh/kh/vs emitted tf32-rounded (cvt_out=1)
    gemm_nt_mma2<<<dim3(DD / 64, MROWS / 128), 256, PROJ_SMEM>>>(q, Wq, qh, MROWS, DD, DD, 1);
    gemm_nt_mma2<<<dim3(DD / 64, MROWS / 128), 256, PROJ_SMEM>>>(k, Wk, kh, MROWS, DD, DD, 1);
    gemm_nt_mma2<<<dim3(DK / 64, MROWS / 128), 256, PROJ_SMEM>>>(v, Wv, vs, MROWS, DK, DD, 1);

    attn_sums_kernel<<<dim3(SS / 128, NH, NB), 256, SUMS_SMEM>>>(qh, kh, rsuminv);

    attn_write_kernel<<<dim3(SS / 64, SS / 128, NB), 256, WRITE_SMEM>>>(
        qh, kh, rsuminv, attn, pavg);

    gemm_nn_mma<<<dim3(1, SS / 64, NB), 256>>>(
        pavg, vs, head, SS, DK, SS,
        (size_t)SS * SS, (size_t)SS * DK, (size_t)SS * DK);

    // Final out projection: full fp32 output (cvt_out=0)
    gemm_nt_mma2<<<dim3(DD / 64, MROWS / 128), 256, PROJ_SMEM>>>(head, Wo, out, MROWS, DD, DK, 0);
}